// round 1
// baseline (speedup 1.0000x reference)
#include <cuda_runtime.h>

// HybridMixSTEDecoder: 5 disjoint-group GEMMs (27648x512 @ 512xN_i) + bias,
// scattered into out[b, tp*9+p, joint, c]. Joint groups are disjoint, so the
// reference's count/division is identity and is skipped.
//
// Inputs (metadata order): tokens, W0,b0, W1,b1, W2,b2, W3,b3, W4,b4
//   tokens: (1024, 27, 5, 512) f32
//   Wi: (9*gs_i*3, 512) f32, bi: (9*gs_i*3,) f32
// Output: (1024, 243, 17, 3) f32

#define BM 128
#define KB 32

static __device__ __forceinline__ void ffma2(unsigned long long &acc,
                                             unsigned long long a2,
                                             unsigned long long b2) {
    asm("fma.rn.f32x2 %0, %1, %2, %0;" : "+l"(acc) : "l"(a2), "l"(b2));
}

static __device__ __forceinline__ unsigned long long pack2(float x) {
    unsigned long long r;
    asm("mov.b64 %0, {%1, %1};" : "=l"(r) : "f"(x));
    return r;
}

static __device__ __forceinline__ void unpack2(unsigned long long v, float &lo, float &hi) {
    asm("mov.b64 {%0, %1}, %2;" : "=f"(lo), "=f"(hi) : "l"(v));
}

// Core tiled GEMM + scatter epilogue.
//   N    : real output columns for this group
//   NPAD : N padded so NPAD/16 is an integer pair count per column-group
//   GS   : joints in this group
template<int N, int NPAD, int GS>
static __device__ __forceinline__ void gemm_core(
    const float* __restrict__ tokens,
    const float* __restrict__ Wg,
    const float* __restrict__ bg,
    float* __restrict__ out,
    int gidx,
    const int (&jmap)[5])
{
    constexpr int PAIRS = NPAD / 16;   // f32x2 pairs per thread
    constexpr int CPT   = NPAD / 8;    // columns per thread

    __shared__ float sA[KB][BM];       // [k][row]
    __shared__ float sW[KB][NPAD];     // [k][col]

    const int tid    = threadIdx.x;
    const int row_t  = tid & 31;       // lane -> row within warp (coalesced sA)
    const int col_t  = tid >> 5;       // warp -> column group (broadcast sW)
    const int colbase = col_t * CPT;

    const int m0 = blockIdx.x * BM;
    const float* Abase = tokens + (size_t)m0 * 2560 + gidx * 512;

    unsigned long long acc[4][PAIRS];
    #pragma unroll
    for (int q = 0; q < 4; q++)
        #pragma unroll
        for (int j = 0; j < PAIRS; j++)
            acc[q][j] = 0ull;

    for (int k0 = 0; k0 < 512; k0 += KB) {
        // ---- load A tile: 128 rows x 32 k, as 1024 float4 ----
        #pragma unroll
        for (int it = 0; it < 4; it++) {
            int e  = tid + it * 256;   // 0..1023
            int r  = e & 127;
            int kq = e >> 7;           // 0..7
            float4 v = *(const float4*)(Abase + (size_t)r * 2560 + k0 + kq * 4);
            sA[kq * 4 + 0][r] = v.x;
            sA[kq * 4 + 1][r] = v.y;
            sA[kq * 4 + 2][r] = v.z;
            sA[kq * 4 + 3][r] = v.w;
        }
        // ---- load W tile: NPAD cols x 32 k (zero-pad cols >= N) ----
        for (int e = tid; e < NPAD * 8; e += 256) {
            int n  = e >> 3;
            int kq = e & 7;
            float4 v = make_float4(0.f, 0.f, 0.f, 0.f);
            if (n < N) v = *(const float4*)(Wg + n * 512 + k0 + kq * 4);
            sW[kq * 4 + 0][n] = v.x;
            sW[kq * 4 + 1][n] = v.y;
            sW[kq * 4 + 2][n] = v.z;
            sW[kq * 4 + 3][n] = v.w;
        }
        __syncthreads();

        #pragma unroll 8
        for (int k = 0; k < KB; k++) {
            unsigned long long a2[4];
            #pragma unroll
            for (int q = 0; q < 4; q++)
                a2[q] = pack2(sA[k][row_t + 32 * q]);
            #pragma unroll
            for (int j = 0; j < PAIRS; j++) {
                unsigned long long w2 =
                    *(const unsigned long long*)&sW[k][colbase + 2 * j];
                #pragma unroll
                for (int q = 0; q < 4; q++)
                    ffma2(acc[q][j], a2[q], w2);
            }
        }
        __syncthreads();
    }

    // ---- epilogue: add bias, scatter to out[b, tp*9+p, joint, c] ----
    // Precompute per-column output offset and bias (shared across 4 rows).
    int   coff[CPT];
    float cbias[CPT];
    #pragma unroll
    for (int cc = 0; cc < CPT; cc++) {
        int o = colbase + cc;
        if (o < N) {
            int p   = o / (GS * 3);
            int rem = o - p * (GS * 3);
            int gi  = rem / 3;
            int c   = rem - gi * 3;
            coff[cc]  = p * 51 + jmap[gi] * 3 + c;
            cbias[cc] = bg[o];
        } else {
            coff[cc]  = -1;
            cbias[cc] = 0.f;
        }
    }

    #pragma unroll
    for (int q = 0; q < 4; q++) {
        int m  = m0 + row_t + 32 * q;
        int b  = m / 27;
        int tp = m - b * 27;
        size_t obase = (size_t)b * 12393 + (size_t)tp * 459;  // 459 = 9*51
        #pragma unroll
        for (int j = 0; j < PAIRS; j++) {
            float lo, hi;
            unpack2(acc[q][j], lo, hi);
            int cc = 2 * j;
            if (coff[cc]     >= 0) out[obase + coff[cc]]     = lo + cbias[cc];
            if (coff[cc + 1] >= 0) out[obase + coff[cc + 1]] = hi + cbias[cc + 1];
        }
    }
}

// Group 2: N=135 (gs=5), joints {0,7,8,9,10}
__global__ void __launch_bounds__(256) dec_g2(
    const float* __restrict__ tokens,
    const float* __restrict__ W,
    const float* __restrict__ b,
    float* __restrict__ out)
{
    int jmap[5] = {0, 7, 8, 9, 10};
    gemm_core<135, 144, 5>(tokens, W, b, out, 2, jmap);
}

// Groups 0,1,3,4: N=81 (gs=3), contiguous joints
__global__ void __launch_bounds__(256) dec_g4(
    const float* __restrict__ tokens,
    const float* __restrict__ W0, const float* __restrict__ b0,
    const float* __restrict__ W1, const float* __restrict__ b1,
    const float* __restrict__ W3, const float* __restrict__ b3,
    const float* __restrict__ W4, const float* __restrict__ b4,
    float* __restrict__ out)
{
    const float* W; const float* b; int gidx, jb;
    switch (blockIdx.y) {
        case 0:  W = W0; b = b0; gidx = 0; jb = 1;  break;
        case 1:  W = W1; b = b1; gidx = 1; jb = 4;  break;
        case 2:  W = W3; b = b3; gidx = 3; jb = 11; break;
        default: W = W4; b = b4; gidx = 4; jb = 14; break;
    }
    int jmap[5] = {jb, jb + 1, jb + 2, 0, 0};
    gemm_core<81, 96, 3>(tokens, W, b, out, gidx, jmap);
}

extern "C" void kernel_launch(void* const* d_in, const int* in_sizes, int n_in,
                              void* d_out, int out_size) {
    const float* tokens = (const float*)d_in[0];
    const float* W[5];
    const float* B[5];
    for (int i = 0; i < 5; i++) {
        W[i] = (const float*)d_in[1 + 2 * i];
        B[i] = (const float*)d_in[2 + 2 * i];
    }
    float* out = (float*)d_out;

    // 27648 rows / 128 per block = 216 blocks per group.
    dec_g2<<<216, 256>>>(tokens, W[2], B[2], out);
    dec_g4<<<dim3(216, 4), 256>>>(tokens,
                                  W[0], B[0], W[1], B[1],
                                  W[3], B[3], W[4], B[4], out);
}

// round 3
// speedup vs baseline: 2.8130x; 2.8130x over previous
#include <cuda_runtime.h>
#include <cuda_bf16.h>
#include <stdint.h>

// HybridMixSTEDecoder: 5 disjoint-group GEMMs (27648x512 @ 512xN_i) + bias,
// scattered into out[b, tp*9+p, joint, c]. Joint groups are disjoint, so the
// reference's count/division is identity.
//
// Tensor-core path via arch-agnostic PTX (harness compiles .target sm_103,
// which rejects tcgen05): mma.sync m16n8k16 bf16 with fp32 accum, 3-pass
// hi/lo split for fp32 accuracy:  A*B ~= Ah*Bh + Ah*Bl + Al*Bh.

// Padded group rows: g0..g4 = 88,88,144,88,88 -> 496 rows of 512 bf16.
static __device__ __align__(16) __nv_bfloat16 g_Bh[496 * 512];
static __device__ __align__(16) __nv_bfloat16 g_Bl[496 * 512];

// ---------------- helpers ----------------
static __device__ __forceinline__ uint32_t s2u(const void* p) {
    uint32_t a;
    asm("{ .reg .u64 t; cvta.to.shared.u64 t, %1; cvt.u32.u64 %0, t; }"
        : "=r"(a) : "l"(p));
    return a;
}
static __device__ __forceinline__ uint32_t prmt_hi(uint32_t a, uint32_t b) {
    uint32_t r; asm("prmt.b32 %0, %1, %2, 0x7632;" : "=r"(r) : "r"(a), "r"(b));
    return r;  // [bf16_trunc(b) : bf16_trunc(a)]
}
static __device__ __forceinline__ uint32_t bf16x2_rn(float lo, float hi) {
    uint32_t r; asm("cvt.rn.bf16x2.f32 %0, %1, %2;" : "=r"(r) : "f"(hi), "f"(lo));
    return r;  // low half = lo, high half = hi
}
static __device__ __forceinline__ float trunc_hi_f(float x) {
    return __uint_as_float(__float_as_uint(x) & 0xffff0000u);
}
static __device__ __forceinline__ void ldsm_x4(uint32_t* r, uint32_t addr) {
    asm volatile("ldmatrix.sync.aligned.m8n8.x4.shared.b16 {%0,%1,%2,%3}, [%4];"
        : "=r"(r[0]), "=r"(r[1]), "=r"(r[2]), "=r"(r[3]) : "r"(addr));
}
static __device__ __forceinline__ void ldsm_x2(uint32_t* r, uint32_t addr) {
    asm volatile("ldmatrix.sync.aligned.m8n8.x2.shared.b16 {%0,%1}, [%2];"
        : "=r"(r[0]), "=r"(r[1]) : "r"(addr));
}
static __device__ __forceinline__ void mma_bf16(float* d, const uint32_t* a,
                                                const uint32_t* b) {
    asm volatile(
        "mma.sync.aligned.m16n8k16.row.col.f32.bf16.bf16.f32 "
        "{%0,%1,%2,%3}, {%4,%5,%6,%7}, {%8,%9}, {%0,%1,%2,%3};"
        : "+f"(d[0]), "+f"(d[1]), "+f"(d[2]), "+f"(d[3])
        : "r"(a[0]), "r"(a[1]), "r"(a[2]), "r"(a[3]), "r"(b[0]), "r"(b[1]));
}

// ---------------- prep: W (f32) -> bf16 hi/lo, [n][512] K-major ------------
__global__ void __launch_bounds__(256) prep_B(
    const float* __restrict__ W0, const float* __restrict__ W1,
    const float* __restrict__ W2, const float* __restrict__ W3,
    const float* __restrict__ W4)
{
    int idx = blockIdx.x * 256 + threadIdx.x;   // one thread per (grow, k4)
    if (idx >= 496 * 128) return;
    int grow = idx >> 7;
    int k = (idx & 127) << 2;                   // 4 consecutive k
    int g, n;
    if      (grow <  88) { g = 0; n = grow;       }
    else if (grow < 176) { g = 1; n = grow -  88; }
    else if (grow < 320) { g = 2; n = grow - 176; }
    else if (grow < 408) { g = 3; n = grow - 320; }
    else                 { g = 4; n = grow - 408; }
    const float* Wg = (g == 0) ? W0 : (g == 1) ? W1 : (g == 2) ? W2
                    : (g == 3) ? W3 : W4;
    int Ng = (g == 2) ? 135 : 81;

    float4 v = make_float4(0.f, 0.f, 0.f, 0.f);
    if (n < Ng) v = *(const float4*)(Wg + n * 512 + k);

    uint32_t h01 = prmt_hi(__float_as_uint(v.x), __float_as_uint(v.y));
    uint32_t h23 = prmt_hi(__float_as_uint(v.z), __float_as_uint(v.w));
    uint32_t l01 = bf16x2_rn(v.x - trunc_hi_f(v.x), v.y - trunc_hi_f(v.y));
    uint32_t l23 = bf16x2_rn(v.z - trunc_hi_f(v.z), v.w - trunc_hi_f(v.w));

    *(uint2*)&g_Bh[grow * 512 + k] = make_uint2(h01, h23);
    *(uint2*)&g_Bl[grow * 512 + k] = make_uint2(l01, l23);
}

// ---------------- main core ----------------
// smem layout (bf16 rows padded to 72 elems = 144B -> ldmatrix conflict-free):
//   sAh [128][72], sAl [128][72], sBh [NPAD][72], sBl [NPAD][72]
template<int N, int NPAD, int GS>
static __device__ __forceinline__ void decode_core(
    const float* __restrict__ tokens,
    const __nv_bfloat16* __restrict__ BhT,
    const __nv_bfloat16* __restrict__ BlT,
    const float* __restrict__ bias,
    float* __restrict__ out,
    int gidx, int jb3)
{
    constexpr int NT = NPAD / 8;              // n-tiles per CTA
    constexpr int LDR = 72;                   // smem row stride (bf16)
    constexpr int A_BYTES = 128 * LDR * 2;    // 18432
    constexpr int B_BYTES = NPAD * LDR * 2;

    extern __shared__ char smem_raw[];
    __nv_bfloat16* sAh = (__nv_bfloat16*)smem_raw;
    __nv_bfloat16* sAl = (__nv_bfloat16*)(smem_raw + A_BYTES);
    __nv_bfloat16* sBh = (__nv_bfloat16*)(smem_raw + 2 * A_BYTES);
    __nv_bfloat16* sBl = (__nv_bfloat16*)(smem_raw + 2 * A_BYTES + B_BYTES);
    const uint32_t sAh_u = s2u(sAh), sAl_u = s2u(sAl);
    const uint32_t sBh_u = s2u(sBh), sBl_u = s2u(sBl);

    const int tid  = threadIdx.x;
    const int wid  = tid >> 5;
    const int lane = tid & 31;

    const int m0 = blockIdx.x * 128;
    const float* Abase = tokens + (size_t)m0 * 2560 + gidx * 512;

    // ldmatrix lane addressing
    const int rowA = 16 * wid + (lane & 7) + (lane & 8);
    const int colA = (lane & 16) ? 8 : 0;
    const uint32_t offA0 = (uint32_t)(rowA * LDR + colA) * 2;
    const uint32_t offB0 = (uint32_t)((lane & 7) * LDR + ((lane & 8) ? 8 : 0)) * 2;

    float acc[NT][4];
    #pragma unroll
    for (int t = 0; t < NT; t++)
        #pragma unroll
        for (int q = 0; q < 4; q++) acc[t][q] = 0.f;

    #pragma unroll 1
    for (int kc = 0; kc < 8; kc++) {
        // ---- load + split-convert A chunk: 128 rows x 64 k ----
        #pragma unroll
        for (int i = 0; i < 8; i++) {
            int e  = tid + i * 256;           // 0..2047
            int r  = e >> 4;
            int fc = e & 15;
            float4 v = *(const float4*)(Abase + (size_t)r * 2560 + kc * 64 + fc * 4);
            uint32_t h01 = prmt_hi(__float_as_uint(v.x), __float_as_uint(v.y));
            uint32_t h23 = prmt_hi(__float_as_uint(v.z), __float_as_uint(v.w));
            uint32_t l01 = bf16x2_rn(v.x - trunc_hi_f(v.x), v.y - trunc_hi_f(v.y));
            uint32_t l23 = bf16x2_rn(v.z - trunc_hi_f(v.z), v.w - trunc_hi_f(v.w));
            int d = r * LDR + fc * 4;
            *(uint2*)&sAh[d] = make_uint2(h01, h23);
            *(uint2*)&sAl[d] = make_uint2(l01, l23);
        }
        // ---- copy B chunk: NPAD rows x 64 k (bf16, pre-converted) ----
        #pragma unroll
        for (int e = tid; e < NPAD * 8; e += 256) {
            int n = e >> 3;
            int q = e & 7;
            int s = n * 512 + kc * 64 + q * 8;
            int d = n * LDR + q * 8;
            *(uint4*)&sBh[d] = *(const uint4*)&BhT[s];
            *(uint4*)&sBl[d] = *(const uint4*)&BlT[s];
        }
        __syncthreads();

        // ---- 4 k16 steps ----
        #pragma unroll
        for (int j = 0; j < 4; j++) {
            uint32_t ah[4], al[4];
            ldsm_x4(ah, sAh_u + offA0 + j * 32);
            ldsm_x4(al, sAl_u + offA0 + j * 32);
            #pragma unroll
            for (int t = 0; t < NT; t++) {
                uint32_t bh[2], bl[2];
                uint32_t ob = offB0 + (uint32_t)(t * 8 * LDR + 16 * j) * 2;
                ldsm_x2(bh, sBh_u + ob);
                ldsm_x2(bl, sBl_u + ob);
                mma_bf16(acc[t], ah, bh);
                mma_bf16(acc[t], ah, bl);
                mma_bf16(acc[t], al, bh);
            }
        }
        __syncthreads();
    }

    // ---- epilogue: bias + scatter ----
    const int g   = lane >> 2;
    const int tig = lane & 3;

    int   coff[NT][2];
    float cb[NT][2];
    #pragma unroll
    for (int t = 0; t < NT; t++) {
        #pragma unroll
        for (int h = 0; h < 2; h++) {
            int o = 8 * t + 2 * tig + h;
            if (o < N) {
                int p   = o / (GS * 3);
                int rem = o - p * (GS * 3);
                int joff = (GS == 5) ? ((rem < 3) ? rem : rem + 18) : (jb3 + rem);
                coff[t][h] = p * 51 + joff;
                cb[t][h]   = bias[o];
            } else {
                coff[t][h] = -1;
                cb[t][h]   = 0.f;
            }
        }
    }

    #pragma unroll
    for (int half = 0; half < 2; half++) {
        int m  = m0 + 16 * wid + g + 8 * half;
        int b  = m / 27;
        int tp = m - b * 27;
        size_t obase = (size_t)b * 12393 + (size_t)tp * 459;
        #pragma unroll
        for (int t = 0; t < NT; t++) {
            float v0 = acc[t][2 * half];
            float v1 = acc[t][2 * half + 1];
            if (coff[t][0] >= 0) out[obase + coff[t][0]] = v0 + cb[t][0];
            if (coff[t][1] >= 0) out[obase + coff[t][1]] = v1 + cb[t][1];
        }
    }
}

// Groups 0,1,3,4: N=81 (gs=3), contiguous joints
__global__ void __launch_bounds__(256, 2) dec_g4(
    const float* __restrict__ tokens,
    const float* __restrict__ b0, const float* __restrict__ b1,
    const float* __restrict__ b3, const float* __restrict__ b4,
    float* __restrict__ out)
{
    int rowbase, gidx, jb3;
    const float* bias;
    switch (blockIdx.y) {
        case 0:  rowbase = 0;   gidx = 0; jb3 = 3;  bias = b0; break;
        case 1:  rowbase = 88;  gidx = 1; jb3 = 12; bias = b1; break;
        case 2:  rowbase = 320; gidx = 3; jb3 = 33; bias = b3; break;
        default: rowbase = 408; gidx = 4; jb3 = 42; bias = b4; break;
    }
    decode_core<81, 88, 3>(tokens, g_Bh + rowbase * 512, g_Bl + rowbase * 512,
                           bias, out, gidx, jb3);
}

// Group 2: N=135 (gs=5), joints {0,7,8,9,10}
__global__ void __launch_bounds__(256, 2) dec_g2(
    const float* __restrict__ tokens,
    const float* __restrict__ b2,
    float* __restrict__ out)
{
    decode_core<135, 144, 5>(tokens, g_Bh + 176 * 512, g_Bl + 176 * 512,
                             b2, out, 2, 0);
}

extern "C" void kernel_launch(void* const* d_in, const int* in_sizes, int n_in,
                              void* d_out, int out_size) {
    const float* tokens = (const float*)d_in[0];
    const float* W[5];
    const float* B[5];
    for (int i = 0; i < 5; i++) {
        W[i] = (const float*)d_in[1 + 2 * i];
        B[i] = (const float*)d_in[2 + 2 * i];
    }
    float* out = (float*)d_out;

    // dyn smem: 2*A(18432) + 2*B(NPAD*144)
    const int smem_g4 = 2 * 18432 + 2 * 88 * 144;    // 62208
    const int smem_g2 = 2 * 18432 + 2 * 144 * 144;   // 78336
    cudaFuncSetAttribute(dec_g4, cudaFuncAttributeMaxDynamicSharedMemorySize, smem_g4);
    cudaFuncSetAttribute(dec_g2, cudaFuncAttributeMaxDynamicSharedMemorySize, smem_g2);

    prep_B<<<(496 * 128 + 255) / 256, 256>>>(W[0], W[1], W[2], W[3], W[4]);
    dec_g2<<<216, 256, smem_g2>>>(tokens, B[2], out);
    dec_g4<<<dim3(216, 4), 256, smem_g4>>>(tokens, B[0], B[1], B[3], B[4], out);
}

// round 4
// speedup vs baseline: 3.2910x; 1.1699x over previous
#include <cuda_runtime.h>
#include <cuda_bf16.h>
#include <stdint.h>

// HybridMixSTEDecoder: 5 disjoint-group GEMMs (27648x512 @ 512xN_i) + bias,
// scattered into out[b, tp*9+p, joint, c]. Groups are disjoint -> the
// reference's count/division is identity.
//
// bf16-split mma.sync (A*B ~= Ah*Bh + Ah*Bl + Al*Bh, fp32 accum) with a
// single fused kernel, double-buffered smem, reg-prefetched A, cp.async B.

// Padded group rows: g0..g4 = 88,88,144,88,88 -> 496 rows of 512 bf16 (linear).
static __device__ __align__(16) __nv_bfloat16 g_Bh[496 * 512];
static __device__ __align__(16) __nv_bfloat16 g_Bl[496 * 512];

// ---------------- helpers ----------------
static __device__ __forceinline__ uint32_t s2u(const void* p) {
    uint32_t a;
    asm("{ .reg .u64 t; cvta.to.shared.u64 t, %1; cvt.u32.u64 %0, t; }"
        : "=r"(a) : "l"(p));
    return a;
}
static __device__ __forceinline__ uint32_t prmt_hi(uint32_t a, uint32_t b) {
    uint32_t r; asm("prmt.b32 %0, %1, %2, 0x7632;" : "=r"(r) : "r"(a), "r"(b));
    return r;  // [bf16_trunc(b) : bf16_trunc(a)]
}
static __device__ __forceinline__ uint32_t bf16x2_rn(float lo, float hi) {
    uint32_t r; asm("cvt.rn.bf16x2.f32 %0, %1, %2;" : "=r"(r) : "f"(hi), "f"(lo));
    return r;
}
static __device__ __forceinline__ float trunc_hi_f(float x) {
    return __uint_as_float(__float_as_uint(x) & 0xffff0000u);
}
static __device__ __forceinline__ void ldsm_x4(uint32_t* r, uint32_t addr) {
    asm volatile("ldmatrix.sync.aligned.m8n8.x4.shared.b16 {%0,%1,%2,%3}, [%4];"
        : "=r"(r[0]), "=r"(r[1]), "=r"(r[2]), "=r"(r[3]) : "r"(addr));
}
static __device__ __forceinline__ void ldsm_x2(uint32_t* r, uint32_t addr) {
    asm volatile("ldmatrix.sync.aligned.m8n8.x2.shared.b16 {%0,%1}, [%2];"
        : "=r"(r[0]), "=r"(r[1]) : "r"(addr));
}
static __device__ __forceinline__ void mma_bf16(float* d, const uint32_t* a,
                                                const uint32_t* b) {
    asm volatile(
        "mma.sync.aligned.m16n8k16.row.col.f32.bf16.bf16.f32 "
        "{%0,%1,%2,%3}, {%4,%5,%6,%7}, {%8,%9}, {%0,%1,%2,%3};"
        : "+f"(d[0]), "+f"(d[1]), "+f"(d[2]), "+f"(d[3])
        : "r"(a[0]), "r"(a[1]), "r"(a[2]), "r"(a[3]), "r"(b[0]), "r"(b[1]));
}
static __device__ __forceinline__ void cp16(uint32_t dst, const void* src, int pred) {
    asm volatile(
        "{\n\t.reg .pred p;\n\tsetp.ne.b32 p, %0, 0;\n\t"
        "@p cp.async.cg.shared.global [%1], [%2], 16;\n\t}"
        :: "r"(pred), "r"(dst), "l"(src));
}

// ---------------- prep: W (f32) -> bf16 hi/lo, [n][512] K-major linear ------
__global__ void __launch_bounds__(256) prep_B(
    const float* __restrict__ W0, const float* __restrict__ W1,
    const float* __restrict__ W2, const float* __restrict__ W3,
    const float* __restrict__ W4)
{
    int idx = blockIdx.x * 256 + threadIdx.x;   // one thread per (grow, k4)
    if (idx >= 496 * 128) return;
    int grow = idx >> 7;
    int k = (idx & 127) << 2;
    int g, n;
    if      (grow <  88) { g = 0; n = grow;       }
    else if (grow < 176) { g = 1; n = grow -  88; }
    else if (grow < 320) { g = 2; n = grow - 176; }
    else if (grow < 408) { g = 3; n = grow - 320; }
    else                 { g = 4; n = grow - 408; }
    const float* Wg = (g == 0) ? W0 : (g == 1) ? W1 : (g == 2) ? W2
                    : (g == 3) ? W3 : W4;
    int Ng = (g == 2) ? 135 : 81;

    float4 v = make_float4(0.f, 0.f, 0.f, 0.f);
    if (n < Ng) v = *(const float4*)(Wg + n * 512 + k);

    uint32_t h01 = prmt_hi(__float_as_uint(v.x), __float_as_uint(v.y));
    uint32_t h23 = prmt_hi(__float_as_uint(v.z), __float_as_uint(v.w));
    uint32_t l01 = bf16x2_rn(v.x - trunc_hi_f(v.x), v.y - trunc_hi_f(v.y));
    uint32_t l23 = bf16x2_rn(v.z - trunc_hi_f(v.z), v.w - trunc_hi_f(v.w));

    *(uint2*)&g_Bh[grow * 512 + k] = make_uint2(h01, h23);
    *(uint2*)&g_Bl[grow * 512 + k] = make_uint2(l01, l23);
}

// ---------------- fused core ----------------
// Smem stage (bytes): Ah 16384 | Al 16384 | Bh NPAD*128 | Bl NPAD*128.
// 128B rows, XOR swizzle on 16B units: phys_u = u ^ (row & 7).
template<int NPAD, int GS, int CO>
static __device__ __forceinline__ void decode_core(
    const float* __restrict__ tokens,
    const __nv_bfloat16* __restrict__ BhT,
    const __nv_bfloat16* __restrict__ BlT,
    const float* __restrict__ bias,
    float* __restrict__ out,
    int gidx, int jb3)
{
    constexpr int NT    = NPAD / 8;
    constexpr int PAIRS = NT / 2;
    constexpr int ODD   = NT & 1;
    constexpr int NREAL = (GS == 5) ? 135 : 81;
    constexpr int BB    = NPAD * 128;          // B tile bytes (per h/l)
    constexpr int STAGE = 32768 + 2 * BB;
    constexpr int NB8   = NPAD * 8;            // cp.async 16B ops per h/l
    constexpr int CPIT  = (NB8 + 255) / 256;

    extern __shared__ char smem[];
    const uint32_t su = s2u(smem);

    const int tid  = threadIdx.x;
    const int wid  = tid >> 5;
    const int lane = tid & 31;

    const int m0 = blockIdx.x * 128;
    const float* Abase = tokens + (size_t)m0 * 2560 + gidx * 512;

    // per-thread A load / store geometry
    const int r0 = tid >> 4;                   // 0..15 (row within 16-row slab)
    const int fc = tid & 15;                   // float4 index within 64-elem row
    const float* aptr = Abase + (size_t)r0 * 2560 + fc * 4;
    const uint32_t stA0 = (uint32_t)(r0 * 128 + (((fc >> 1) ^ (r0 & 7)) << 4)
                                     + (fc & 1) * 8);

    // ldmatrix geometry
    const int rA   = 16 * wid + (lane & 15);
    const int kuA  = lane >> 4;                        // 0/1
    const int rBo  = (lane & 7) + ((lane & 16) ? 8 : 0);
    const int kuB  = (lane >> 3) & 1;
    const int sw   = lane & 7;                         // xor term (row&7)

    float acc[NT][4];
    #pragma unroll
    for (int t = 0; t < NT; t++)
        #pragma unroll
        for (int q = 0; q < 4; q++) acc[t][q] = 0.f;

    // ---- prologue: A(0) regs, B(0) cp.async ----
    uint4 ra[8];
    #pragma unroll
    for (int i = 0; i < 8; i++)
        ra[i] = *(const uint4*)(aptr + (size_t)i * 40960);
    {
        const uint32_t bh0 = su + 32768;
        const uint32_t bl0 = su + 32768 + BB;
        #pragma unroll
        for (int jj = 0; jj < CPIT; jj++) {
            int idx = tid + jj * 256;
            int v = idx < NB8;
            int n = idx >> 3, q = idx & 7;
            uint32_t d = (uint32_t)(n * 128 + ((q ^ (n & 7)) << 4));
            cp16(bh0 + d, BhT + n * 512 + q * 8, v);
            cp16(bl0 + d, BlT + n * 512 + q * 8, v);
        }
        asm volatile("cp.async.commit_group;" ::: "memory");
    }

    #pragma unroll 1
    for (int kc = 0; kc < 8; kc++) {
        const int s = kc & 1;
        const uint32_t sb = su + s * STAGE;

        // 1) convert + store A(kc) into stage s
        #pragma unroll
        for (int i = 0; i < 8; i++) {
            uint32_t h01 = prmt_hi(ra[i].x, ra[i].y);
            uint32_t h23 = prmt_hi(ra[i].z, ra[i].w);
            float fx = __uint_as_float(ra[i].x), fy = __uint_as_float(ra[i].y);
            float fz = __uint_as_float(ra[i].z), fw = __uint_as_float(ra[i].w);
            uint32_t l01 = bf16x2_rn(fx - trunc_hi_f(fx), fy - trunc_hi_f(fy));
            uint32_t l23 = bf16x2_rn(fz - trunc_hi_f(fz), fw - trunc_hi_f(fw));
            uint32_t off = stA0 + (uint32_t)i * 2048;
            *(uint2*)(smem + (s * STAGE) + off)         = make_uint2(h01, h23);
            *(uint2*)(smem + (s * STAGE) + 16384 + off) = make_uint2(l01, l23);
        }
        // 2) prefetch A(kc+1) into regs (in flight across barrier + MMA)
        if (kc < 7) {
            #pragma unroll
            for (int i = 0; i < 8; i++)
                ra[i] = *(const uint4*)(aptr + (kc + 1) * 64 + (size_t)i * 40960);
        }
        // 3) drain B(kc); publish stage s
        asm volatile("cp.async.wait_group 0;" ::: "memory");
        __syncthreads();
        // 4) issue B(kc+1) into stage s^1 (safe: all warps done reading it)
        if (kc < 7) {
            const uint32_t bh1 = su + (s ^ 1) * STAGE + 32768;
            const uint32_t bl1 = bh1 + BB;
            const __nv_bfloat16* bhs = BhT + (kc + 1) * 64;
            const __nv_bfloat16* bls = BlT + (kc + 1) * 64;
            #pragma unroll
            for (int jj = 0; jj < CPIT; jj++) {
                int idx = tid + jj * 256;
                int v = idx < NB8;
                int n = idx >> 3, q = idx & 7;
                uint32_t d = (uint32_t)(n * 128 + ((q ^ (n & 7)) << 4));
                cp16(bh1 + d, bhs + n * 512 + q * 8, v);
                cp16(bl1 + d, bls + n * 512 + q * 8, v);
            }
            asm volatile("cp.async.commit_group;" ::: "memory");
        }
        // 5) MMA on stage s
        const uint32_t aBase = sb + (uint32_t)rA * 128;
        const uint32_t bBase = sb + 32768;
        #pragma unroll
        for (int j = 0; j < 4; j++) {
            uint32_t au = (uint32_t)(((2 * j + kuA) ^ sw) << 4);
            uint32_t ah[4], al[4];
            ldsm_x4(ah, aBase + au);
            ldsm_x4(al, aBase + 16384 + au);
            uint32_t bu = (uint32_t)(((2 * j + kuB) ^ sw) << 4);
            #pragma unroll
            for (int p = 0; p < PAIRS; p++) {
                uint32_t boff = (uint32_t)((16 * p + rBo) * 128) + bu;
                uint32_t bh[4], bl[4];
                ldsm_x4(bh, bBase + boff);
                ldsm_x4(bl, bBase + BB + boff);
                mma_bf16(acc[2 * p],     ah, bh);
                mma_bf16(acc[2 * p],     ah, bl);
                mma_bf16(acc[2 * p],     al, bh);
                mma_bf16(acc[2 * p + 1], ah, bh + 2);
                mma_bf16(acc[2 * p + 1], ah, bl + 2);
                mma_bf16(acc[2 * p + 1], al, bh + 2);
            }
            if (ODD) {
                uint32_t boff = (uint32_t)((16 * PAIRS + (lane & 7)) * 128) + bu;
                uint32_t bh[2], bl[2];
                ldsm_x2(bh, bBase + boff);
                ldsm_x2(bl, bBase + BB + boff);
                mma_bf16(acc[NT - 1], ah, bh);
                mma_bf16(acc[NT - 1], ah, bl);
                mma_bf16(acc[NT - 1], al, bh);
            }
        }
    }

    // ---- epilogue: bias + scatter ----
    const int g   = lane >> 2;
    const int tig = lane & 3;

    int   coff[NT][2];
    float cb[NT][2];
    #pragma unroll
    for (int t = 0; t < NT; t++) {
        #pragma unroll
        for (int h = 0; h < 2; h++) {
            int o = CO + 8 * t + 2 * tig + h;
            if (o < NREAL) {
                int p   = o / (GS * 3);
                int rem = o - p * (GS * 3);
                int joff = (GS == 5) ? ((rem < 3) ? rem : rem + 18) : (jb3 + rem);
                coff[t][h] = p * 51 + joff;
                cb[t][h]   = bias[o];
            } else {
                coff[t][h] = -1;
                cb[t][h]   = 0.f;
            }
        }
    }

    #pragma unroll
    for (int half = 0; half < 2; half++) {
        int m  = m0 + 16 * wid + g + 8 * half;
        int b  = m / 27;
        int tp = m - b * 27;
        size_t obase = (size_t)b * 12393 + (size_t)tp * 459;
        #pragma unroll
        for (int t = 0; t < NT; t++) {
            float v0 = acc[t][2 * half];
            float v1 = acc[t][2 * half + 1];
            if (coff[t][0] >= 0) out[obase + coff[t][0]] = v0 + cb[t][0];
            if (coff[t][1] >= 0) out[obase + coff[t][1]] = v1 + cb[t][1];
        }
    }
}

// One fused kernel: y 0..3 -> groups 0,1,3,4 (NPAD=88); y 4,5 -> group 2 halves.
__global__ void __launch_bounds__(256, 2) dec_all(
    const float* __restrict__ tokens,
    const float* __restrict__ b0, const float* __restrict__ b1,
    const float* __restrict__ b2, const float* __restrict__ b3,
    const float* __restrict__ b4,
    float* __restrict__ out)
{
    int y = blockIdx.y;
    if (y < 4) {
        int rowbase, gidx, jb3;
        const float* bias;
        switch (y) {
            case 0:  rowbase = 0;   gidx = 0; jb3 = 3;  bias = b0; break;
            case 1:  rowbase = 88;  gidx = 1; jb3 = 12; bias = b1; break;
            case 2:  rowbase = 320; gidx = 3; jb3 = 33; bias = b3; break;
            default: rowbase = 408; gidx = 4; jb3 = 42; bias = b4; break;
        }
        decode_core<88, 3, 0>(tokens, g_Bh + rowbase * 512, g_Bl + rowbase * 512,
                              bias, out, gidx, jb3);
    } else if (y == 4) {
        decode_core<72, 5, 0>(tokens, g_Bh + 176 * 512, g_Bl + 176 * 512,
                              b2, out, 2, 0);
    } else {
        decode_core<72, 5, 72>(tokens, g_Bh + 248 * 512, g_Bl + 248 * 512,
                               b2, out, 2, 0);
    }
}

extern "C" void kernel_launch(void* const* d_in, const int* in_sizes, int n_in,
                              void* d_out, int out_size) {
    const float* tokens = (const float*)d_in[0];
    const float* W[5];
    const float* B[5];
    for (int i = 0; i < 5; i++) {
        W[i] = (const float*)d_in[1 + 2 * i];
        B[i] = (const float*)d_in[2 + 2 * i];
    }
    float* out = (float*)d_out;

    // dyn smem: 2 stages of (32768 + 2*88*128) = 110592 bytes (2 CTAs/SM fits 228KB)
    const int smem_sz = 2 * (32768 + 2 * 88 * 128);
    cudaFuncSetAttribute(dec_all, cudaFuncAttributeMaxDynamicSharedMemorySize, smem_sz);

    prep_B<<<(496 * 128 + 255) / 256, 256>>>(W[0], W[1], W[2], W[3], W[4]);
    dec_all<<<dim3(216, 6), 256, smem_sz>>>(tokens, B[0], B[1], B[2], B[3], B[4], out);
}

// round 5
// speedup vs baseline: 4.5365x; 1.3785x over previous
#include <cuda_runtime.h>
#include <cuda_fp16.h>
#include <stdint.h>

// HybridMixSTEDecoder: 5 disjoint-group GEMMs (27648x512 @ 512xN_i) + bias,
// scattered into out[b, tp*9+p, joint, c]. Groups disjoint -> count/div is identity.
//
// fp16 2-pass split: A = Ah + Al (fp16 hi/lo, exact to ~2^-22), B rounded once
// to fp16.  D = Ah*Bh + Al*Bh  (fp32 accum). Error ~ B's fp16 rounding ~ 5e-4.

// Padded group rows: g0..g4 = 88,88,144,88,88 -> 496 rows of 512 fp16.
static __device__ __align__(16) __half g_Bh[496 * 512];

// ---------------- helpers ----------------
static __device__ __forceinline__ uint32_t s2u(const void* p) {
    uint32_t a;
    asm("{ .reg .u64 t; cvta.to.shared.u64 t, %1; cvt.u32.u64 %0, t; }"
        : "=r"(a) : "l"(p));
    return a;
}
static __device__ __forceinline__ uint32_t f16x2_rn(float lo, float hi) {
    uint32_t r; asm("cvt.rn.f16x2.f32 %0, %1, %2;" : "=r"(r) : "f"(hi), "f"(lo));
    return r;  // low half = lo, high half = hi
}
static __device__ __forceinline__ void ldsm_x4(uint32_t* r, uint32_t addr) {
    asm volatile("ldmatrix.sync.aligned.m8n8.x4.shared.b16 {%0,%1,%2,%3}, [%4];"
        : "=r"(r[0]), "=r"(r[1]), "=r"(r[2]), "=r"(r[3]) : "r"(addr));
}
static __device__ __forceinline__ void ldsm_x2(uint32_t* r, uint32_t addr) {
    asm volatile("ldmatrix.sync.aligned.m8n8.x2.shared.b16 {%0,%1}, [%2];"
        : "=r"(r[0]), "=r"(r[1]) : "r"(addr));
}
static __device__ __forceinline__ void mma_f16(float* d, const uint32_t* a,
                                               const uint32_t* b) {
    asm volatile(
        "mma.sync.aligned.m16n8k16.row.col.f32.f16.f16.f32 "
        "{%0,%1,%2,%3}, {%4,%5,%6,%7}, {%8,%9}, {%0,%1,%2,%3};"
        : "+f"(d[0]), "+f"(d[1]), "+f"(d[2]), "+f"(d[3])
        : "r"(a[0]), "r"(a[1]), "r"(a[2]), "r"(a[3]), "r"(b[0]), "r"(b[1]));
}
static __device__ __forceinline__ void cp16(uint32_t dst, const void* src, int pred) {
    asm volatile(
        "{\n\t.reg .pred p;\n\tsetp.ne.b32 p, %0, 0;\n\t"
        "@p cp.async.cg.shared.global [%1], [%2], 16;\n\t}"
        :: "r"(pred), "r"(dst), "l"(src));
}

// ---------------- prep: W (f32) -> fp16 (RN), [n][512] K-major linear -------
__global__ void __launch_bounds__(256) prep_B(
    const float* __restrict__ W0, const float* __restrict__ W1,
    const float* __restrict__ W2, const float* __restrict__ W3,
    const float* __restrict__ W4)
{
    int idx = blockIdx.x * 256 + threadIdx.x;   // one thread per (grow, k4)
    if (idx >= 496 * 128) return;
    int grow = idx >> 7;
    int k = (idx & 127) << 2;
    int g, n;
    if      (grow <  88) { g = 0; n = grow;       }
    else if (grow < 176) { g = 1; n = grow -  88; }
    else if (grow < 320) { g = 2; n = grow - 176; }
    else if (grow < 408) { g = 3; n = grow - 320; }
    else                 { g = 4; n = grow - 408; }
    const float* Wg = (g == 0) ? W0 : (g == 1) ? W1 : (g == 2) ? W2
                    : (g == 3) ? W3 : W4;
    int Ng = (g == 2) ? 135 : 81;

    float4 v = make_float4(0.f, 0.f, 0.f, 0.f);
    if (n < Ng) v = *(const float4*)(Wg + n * 512 + k);

    uint32_t h01 = f16x2_rn(v.x, v.y);
    uint32_t h23 = f16x2_rn(v.z, v.w);
    *(uint2*)&g_Bh[grow * 512 + k] = make_uint2(h01, h23);
}

// ---------------- fused core ----------------
// Smem stage (bytes): Ah 16384 | Al 16384 | Bh NPAD*128.
// 128B rows, XOR swizzle on 16B units: phys_u = u ^ (row & 7).
template<int NPAD, int GS, int CO>
static __device__ __forceinline__ void decode_core(
    const float* __restrict__ tokens,
    const __half* __restrict__ BhT,
    const float* __restrict__ bias,
    float* __restrict__ out,
    int gidx, int jb3)
{
    constexpr int NT    = NPAD / 8;
    constexpr int PAIRS = NT / 2;
    constexpr int ODD   = NT & 1;
    constexpr int NREAL = (GS == 5) ? 135 : 81;
    constexpr int BB    = NPAD * 128;          // B tile bytes
    constexpr int STAGE = 32768 + BB;
    constexpr int NB8   = NPAD * 8;            // cp.async 16B ops
    constexpr int CPIT  = (NB8 + 255) / 256;

    extern __shared__ char smem[];
    const uint32_t su = s2u(smem);

    const int tid  = threadIdx.x;
    const int wid  = tid >> 5;
    const int lane = tid & 31;

    const int m0 = blockIdx.x * 128;
    const float* Abase = tokens + (size_t)m0 * 2560 + gidx * 512;

    // per-thread A load / store geometry
    const int r0 = tid >> 4;                   // 0..15 (row within 16-row slab)
    const int fc = tid & 15;                   // float4 index within 64-elem row
    const float* aptr = Abase + (size_t)r0 * 2560 + fc * 4;
    const uint32_t stA0 = (uint32_t)(r0 * 128 + (((fc >> 1) ^ (r0 & 7)) << 4)
                                     + (fc & 1) * 8);

    // ldmatrix geometry
    const int rA   = 16 * wid + (lane & 15);
    const int kuA  = lane >> 4;                        // 0/1
    const int rBo  = (lane & 7) + ((lane & 16) ? 8 : 0);
    const int kuB  = (lane >> 3) & 1;
    const int sw   = lane & 7;                         // xor term (row&7)

    float acc[NT][4];
    #pragma unroll
    for (int t = 0; t < NT; t++)
        #pragma unroll
        for (int q = 0; q < 4; q++) acc[t][q] = 0.f;

    // ---- prologue: A(0) regs, B(0) cp.async ----
    uint4 ra[8];
    #pragma unroll
    for (int i = 0; i < 8; i++)
        ra[i] = *(const uint4*)(aptr + (size_t)i * 40960);
    {
        const uint32_t bh0 = su + 32768;
        #pragma unroll
        for (int jj = 0; jj < CPIT; jj++) {
            int idx = tid + jj * 256;
            int v = idx < NB8;
            int n = idx >> 3, q = idx & 7;
            uint32_t d = (uint32_t)(n * 128 + ((q ^ (n & 7)) << 4));
            cp16(bh0 + d, BhT + n * 512 + q * 8, v);
        }
        asm volatile("cp.async.commit_group;" ::: "memory");
    }

    #pragma unroll 1
    for (int kc = 0; kc < 8; kc++) {
        const int s = kc & 1;
        const uint32_t sb = su + s * STAGE;

        // 1) convert + store A(kc) into stage s (fp16 hi/lo split)
        #pragma unroll
        for (int i = 0; i < 8; i++) {
            float fx = __uint_as_float(ra[i].x), fy = __uint_as_float(ra[i].y);
            float fz = __uint_as_float(ra[i].z), fw = __uint_as_float(ra[i].w);
            uint32_t h01 = f16x2_rn(fx, fy);
            uint32_t h23 = f16x2_rn(fz, fw);
            __half2 a01 = *(__half2*)&h01;
            __half2 a23 = *(__half2*)&h23;
            uint32_t l01 = f16x2_rn(fx - __low2float(a01), fy - __high2float(a01));
            uint32_t l23 = f16x2_rn(fz - __low2float(a23), fw - __high2float(a23));
            uint32_t off = stA0 + (uint32_t)i * 2048;
            *(uint2*)(smem + (s * STAGE) + off)         = make_uint2(h01, h23);
            *(uint2*)(smem + (s * STAGE) + 16384 + off) = make_uint2(l01, l23);
        }
        // 2) prefetch A(kc+1) into regs (in flight across barrier + MMA)
        if (kc < 7) {
            #pragma unroll
            for (int i = 0; i < 8; i++)
                ra[i] = *(const uint4*)(aptr + (kc + 1) * 64 + (size_t)i * 40960);
        }
        // 3) drain B(kc); publish stage s
        asm volatile("cp.async.wait_group 0;" ::: "memory");
        __syncthreads();
        // 4) issue B(kc+1) into stage s^1 (safe: all warps done reading it)
        if (kc < 7) {
            const uint32_t bh1 = su + (s ^ 1) * STAGE + 32768;
            const __half* bhs = BhT + (kc + 1) * 64;
            #pragma unroll
            for (int jj = 0; jj < CPIT; jj++) {
                int idx = tid + jj * 256;
                int v = idx < NB8;
                int n = idx >> 3, q = idx & 7;
                uint32_t d = (uint32_t)(n * 128 + ((q ^ (n & 7)) << 4));
                cp16(bh1 + d, bhs + n * 512 + q * 8, v);
            }
            asm volatile("cp.async.commit_group;" ::: "memory");
        }
        // 5) MMA on stage s: acc += Ah*Bh + Al*Bh
        const uint32_t aBase = sb + (uint32_t)rA * 128;
        const uint32_t bBase = sb + 32768;
        #pragma unroll
        for (int j = 0; j < 4; j++) {
            uint32_t au = (uint32_t)(((2 * j + kuA) ^ sw) << 4);
            uint32_t ah[4], al[4];
            ldsm_x4(ah, aBase + au);
            ldsm_x4(al, aBase + 16384 + au);
            uint32_t bu = (uint32_t)(((2 * j + kuB) ^ sw) << 4);
            #pragma unroll
            for (int p = 0; p < PAIRS; p++) {
                uint32_t boff = (uint32_t)((16 * p + rBo) * 128) + bu;
                uint32_t bh[4];
                ldsm_x4(bh, bBase + boff);
                mma_f16(acc[2 * p],     ah, bh);
                mma_f16(acc[2 * p],     al, bh);
                mma_f16(acc[2 * p + 1], ah, bh + 2);
                mma_f16(acc[2 * p + 1], al, bh + 2);
            }
            if (ODD) {
                uint32_t boff = (uint32_t)((16 * PAIRS + (lane & 7)) * 128) + bu;
                uint32_t bh[2];
                ldsm_x2(bh, bBase + boff);
                mma_f16(acc[NT - 1], ah, bh);
                mma_f16(acc[NT - 1], al, bh);
            }
        }
    }

    // ---- epilogue: bias + scatter ----
    const int g   = lane >> 2;
    const int tig = lane & 3;

    int   coff[NT][2];
    float cb[NT][2];
    #pragma unroll
    for (int t = 0; t < NT; t++) {
        #pragma unroll
        for (int h = 0; h < 2; h++) {
            int o = CO + 8 * t + 2 * tig + h;
            if (o < NREAL) {
                int p   = o / (GS * 3);
                int rem = o - p * (GS * 3);
                int joff = (GS == 5) ? ((rem < 3) ? rem : rem + 18) : (jb3 + rem);
                coff[t][h] = p * 51 + joff;
                cb[t][h]   = bias[o];
            } else {
                coff[t][h] = -1;
                cb[t][h]   = 0.f;
            }
        }
    }

    #pragma unroll
    for (int half = 0; half < 2; half++) {
        int m  = m0 + 16 * wid + g + 8 * half;
        int b  = m / 27;
        int tp = m - b * 27;
        size_t obase = (size_t)b * 12393 + (size_t)tp * 459;
        #pragma unroll
        for (int t = 0; t < NT; t++) {
            float v0 = acc[t][2 * half];
            float v1 = acc[t][2 * half + 1];
            if (coff[t][0] >= 0) out[obase + coff[t][0]] = v0 + cb[t][0];
            if (coff[t][1] >= 0) out[obase + coff[t][1]] = v1 + cb[t][1];
        }
    }
}

// One fused kernel: y 0..3 -> groups 0,1,3,4 (NPAD=88); y 4,5 -> group 2 halves.
__global__ void __launch_bounds__(256, 2) dec_all(
    const float* __restrict__ tokens,
    const float* __restrict__ b0, const float* __restrict__ b1,
    const float* __restrict__ b2, const float* __restrict__ b3,
    const float* __restrict__ b4,
    float* __restrict__ out)
{
    int y = blockIdx.y;
    if (y < 4) {
        int rowbase, gidx, jb3;
        const float* bias;
        switch (y) {
            case 0:  rowbase = 0;   gidx = 0; jb3 = 3;  bias = b0; break;
            case 1:  rowbase = 88;  gidx = 1; jb3 = 12; bias = b1; break;
            case 2:  rowbase = 320; gidx = 3; jb3 = 33; bias = b3; break;
            default: rowbase = 408; gidx = 4; jb3 = 42; bias = b4; break;
        }
        decode_core<88, 3, 0>(tokens, g_Bh + rowbase * 512, bias, out, gidx, jb3);
    } else if (y == 4) {
        decode_core<72, 5, 0>(tokens, g_Bh + 176 * 512, b2, out, 2, 0);
    } else {
        decode_core<72, 5, 72>(tokens, g_Bh + 248 * 512, b2, out, 2, 0);
    }
}

extern "C" void kernel_launch(void* const* d_in, const int* in_sizes, int n_in,
                              void* d_out, int out_size) {
    const float* tokens = (const float*)d_in[0];
    const float* W[5];
    const float* B[5];
    for (int i = 0; i < 5; i++) {
        W[i] = (const float*)d_in[1 + 2 * i];
        B[i] = (const float*)d_in[2 + 2 * i];
    }
    float* out = (float*)d_out;

    // dyn smem: 2 stages of (32768 + 88*128) = 88064 bytes (2 CTAs/SM)
    const int smem_sz = 2 * (32768 + 88 * 128);
    cudaFuncSetAttribute(dec_all, cudaFuncAttributeMaxDynamicSharedMemorySize, smem_sz);

    prep_B<<<(496 * 128 + 255) / 256, 256>>>(W[0], W[1], W[2], W[3], W[4]);
    dec_all<<<dim3(216, 6), 256, smem_sz>>>(tokens, B[0], B[1], B[2], B[3], B[4], out);
}